// round 7
// baseline (speedup 1.0000x reference)
#include <cuda_runtime.h>
#include <cuda_bf16.h>
#include <cstdint>

// Problem constants
#define RB    8192      // B*S rows
#define DD    2048      // D (= K for both GEMMs)
#define FD    10240     // 5*D
#define HH    16        // heads
#define HDIM  128       // head dim
#define CH    64        // chunk length
#define NCH   64        // number of chunks (S / CH)
#define NCHAN 4096      // B*H*HDIM channels
#define SS    4096      // S

#define BK    32
#define NKC   64        // K chunks (2048/32)
#define STAGE_BYTES 32768
#define NSTAGE 3
#define GEMM_SMEM (NSTAGE * STAGE_BYTES)
#define RMS_EPS 1.1920928955078125e-07f

// ---------------- scratch (device globals; allocation-free) ----------------
__device__ float g_proj[(size_t)RB * FD];            // fp32 proj [8192,10240]
__device__ float g_P [NCH * NCHAN];
__device__ float g_A [NCH * NCHAN];
__device__ float g_S0[NCH * NCHAN];
__device__ __nv_bfloat16 g_xh[(size_t)RB * DD];
__device__ __nv_bfloat16 g_xl[(size_t)RB * DD];
__device__ __nv_bfloat16 g_wih[(size_t)FD * DD];
__device__ __nv_bfloat16 g_wil[(size_t)FD * DD];
__device__ __nv_bfloat16 g_woh[(size_t)DD * DD];
__device__ __nv_bfloat16 g_wol[(size_t)DD * DD];
__device__ __nv_bfloat16 g_yh[(size_t)RB * DD];
__device__ __nv_bfloat16 g_yl[(size_t)RB * DD];

// ---------------- helpers ----------------
__device__ __forceinline__ uint32_t smem_u32(const void* p) {
    uint32_t a;
    asm("{ .reg .u64 t; cvta.to.shared.u64 t, %1; cvt.u32.u64 %0, t; }" : "=r"(a) : "l"(p));
    return a;
}
__device__ __forceinline__ void cpasync16(uint32_t s, const void* g) {
    asm volatile("cp.async.cg.shared.global [%0], [%1], 16;\n" :: "r"(s), "l"(g) : "memory");
}
#define CP_COMMIT() asm volatile("cp.async.commit_group;\n" ::: "memory")
#define CP_WAIT(n)  asm volatile("cp.async.wait_group %0;\n" :: "n"(n) : "memory")

__device__ __forceinline__ void ldsm4(uint32_t& r0, uint32_t& r1, uint32_t& r2, uint32_t& r3, uint32_t a) {
    asm volatile("ldmatrix.sync.aligned.m8n8.x4.shared.b16 {%0,%1,%2,%3}, [%4];"
                 : "=r"(r0), "=r"(r1), "=r"(r2), "=r"(r3) : "r"(a));
}
__device__ __forceinline__ void mma16816(float& c0, float& c1, float& c2, float& c3,
                                         uint32_t a0, uint32_t a1, uint32_t a2, uint32_t a3,
                                         uint32_t b0, uint32_t b1) {
    asm volatile("mma.sync.aligned.m16n8k16.row.col.f32.bf16.bf16.f32 "
                 "{%0,%1,%2,%3}, {%4,%5,%6,%7}, {%8,%9}, {%0,%1,%2,%3};"
                 : "+f"(c0), "+f"(c1), "+f"(c2), "+f"(c3)
                 : "r"(a0), "r"(a1), "r"(a2), "r"(a3), "r"(b0), "r"(b1));
}

// smem tile layout: rows x BK(32) bf16, 4 chunks of 16B per row,
// chunk swizzled by (row>>1)&3 -> ldmatrix phases conflict-free
__device__ __forceinline__ uint32_t tile_off(int row, int c16) {
    return (uint32_t)((row * 4 + (c16 ^ ((row >> 1) & 3))) << 4);
}

__device__ __forceinline__ float sigm(float x) { return 1.0f / (1.0f + expf(-x)); }

// ---------------------------------------------------------------------------
// bf16 split-precision GEMM (TN): C[m,n] = sum_k A[m,k]*B[n,k], K = 2048.
// Ah*Bh + Al*Bh + Ah*Bl via mma.sync m16n8k16, fp32 accum.
// CTA 128x128, BK=32, 3-stage cp.async pipeline, 256 threads, 2 CTAs/SM.
// mode==1 (GEMM1): epilogue applies per-region transforms:
//   region 0 (q): rmsnorm over the 128-col tile (= one full head)
//   region 1 (k): tanh      region 3 (a): clip(sigmoid(x+2), 0.6, 0.9995)
// ---------------------------------------------------------------------------
__global__ __launch_bounds__(256, 2)
void gemm_bf16x3_mma(const __nv_bfloat16* __restrict__ Ah, const __nv_bfloat16* __restrict__ Al,
                     const __nv_bfloat16* __restrict__ Bh, const __nv_bfloat16* __restrict__ Bl,
                     float* __restrict__ C, int nb_n, int ldc, int mode) {
    extern __shared__ char smem[];
    const uint32_t sb = smem_u32(smem);
    const int tid  = threadIdx.x;
    const int wid  = tid >> 5;
    const int lane = tid & 31;

    // supertile swizzle for L2: groups of W m-blocks, m fast
    const int W = 16;
    int id = blockIdx.x;
    int gsize = W * nb_n;
    int g = id / gsize, r = id % gsize;
    int m0 = (g * W + (r % W)) << 7;
    int n0 = (r / W) << 7;

    const int wm = wid & 1;        // 0..1
    const int wn = wid >> 1;       // 0..3

    // per-thread load coords (2 chunks per tile per thread)
    const int lrow0 = tid >> 2;
    const int lc0   = tid & 3;
    const int lrow1 = (tid + 256) >> 2;
    const int lc1   = (tid + 256) & 3;
    const uint32_t so0 = tile_off(lrow0, lc0);
    const uint32_t so1 = tile_off(lrow1, lc1);

#define LOAD_STAGE(sidx, k0)                                                     \
    do {                                                                         \
        uint32_t stb = sb + (sidx) * STAGE_BYTES;                                \
        size_t gA0 = (size_t)(m0 + lrow0) * DD + (k0) + lc0 * 8;                 \
        size_t gA1 = (size_t)(m0 + lrow1) * DD + (k0) + lc1 * 8;                 \
        size_t gB0 = (size_t)(n0 + lrow0) * DD + (k0) + lc0 * 8;                 \
        size_t gB1 = (size_t)(n0 + lrow1) * DD + (k0) + lc1 * 8;                 \
        cpasync16(stb + so0,          Ah + gA0);                                 \
        cpasync16(stb + so1,          Ah + gA1);                                 \
        cpasync16(stb + 8192 + so0,   Al + gA0);                                 \
        cpasync16(stb + 8192 + so1,   Al + gA1);                                 \
        cpasync16(stb + 16384 + so0,  Bh + gB0);                                 \
        cpasync16(stb + 16384 + so1,  Bh + gB1);                                 \
        cpasync16(stb + 24576 + so0,  Bl + gB0);                                 \
        cpasync16(stb + 24576 + so1,  Bl + gB1);                                 \
        CP_COMMIT();                                                             \
    } while (0)

    LOAD_STAGE(0, 0);
    LOAD_STAGE(1, BK);

    float acc[4][4][4];
#pragma unroll
    for (int i = 0; i < 4; i++)
#pragma unroll
        for (int j = 0; j < 4; j++)
#pragma unroll
            for (int q = 0; q < 4; q++) acc[i][j][q] = 0.0f;

    const int lj = lane >> 3;
    const int li = lane & 7;

    for (int it = 0; it < NKC; it++) {
        if (it < NKC - 1) { CP_WAIT(1); } else { CP_WAIT(0); }
        __syncthreads();

        if (it + 2 < NKC) LOAD_STAGE((it + 2) % NSTAGE, (it + 2) * BK);

        uint32_t stb = sb + (it % NSTAGE) * STAGE_BYTES;
        uint32_t sAh = stb, sAl = stb + 8192, sBh = stb + 16384, sBl = stb + 24576;

#pragma unroll
        for (int h = 0; h < 2; h++) {
            uint32_t bh[8], bl[8];
#pragma unroll
            for (int ntp = 0; ntp < 2; ntp++) {
                int brow = wn * 32 + ntp * 16 + ((lj >> 1) * 8) + li;
                int bc16 = 2 * h + (lj & 1);
                uint32_t boff = tile_off(brow, bc16);
                ldsm4(bh[ntp * 4], bh[ntp * 4 + 1], bh[ntp * 4 + 2], bh[ntp * 4 + 3], sBh + boff);
                ldsm4(bl[ntp * 4], bl[ntp * 4 + 1], bl[ntp * 4 + 2], bl[ntp * 4 + 3], sBl + boff);
            }
#pragma unroll
            for (int mt = 0; mt < 4; mt++) {
                int arow = wm * 64 + mt * 16 + ((lj & 1) * 8) + li;
                int ac16 = 2 * h + (lj >> 1);
                uint32_t aoff = tile_off(arow, ac16);
                uint32_t ah0, ah1, ah2, ah3, al0, al1, al2, al3;
                ldsm4(ah0, ah1, ah2, ah3, sAh + aoff);
                ldsm4(al0, al1, al2, al3, sAl + aoff);
#pragma unroll
                for (int ntp = 0; ntp < 2; ntp++) {
#pragma unroll
                    for (int s = 0; s < 2; s++) {
                        int nt = ntp * 2 + s;
                        uint32_t b0h = bh[ntp * 4 + s * 2], b1h = bh[ntp * 4 + s * 2 + 1];
                        uint32_t b0l = bl[ntp * 4 + s * 2], b1l = bl[ntp * 4 + s * 2 + 1];
                        float* a_ = acc[mt][nt];
                        mma16816(a_[0], a_[1], a_[2], a_[3], ah0, ah1, ah2, ah3, b0h, b1h);
                        mma16816(a_[0], a_[1], a_[2], a_[3], al0, al1, al2, al3, b0h, b1h);
                        mma16816(a_[0], a_[1], a_[2], a_[3], ah0, ah1, ah2, ah3, b0l, b1l);
                    }
                }
            }
        }
    }

    const int gq  = lane >> 2;
    const int tig = lane & 3;

    // ---- fused prep transforms (GEMM1 only) ----
    int region = (mode == 1) ? (n0 >> 11) : -1;
    if (region == 0) {
        // rmsnorm: this 128-col tile is one full head; row sums via quad shfl
        // + cross-warp smem reduction.
        float s1[4], s2[4];
#pragma unroll
        for (int mt = 0; mt < 4; mt++) {
            float a1 = 0.0f, a2 = 0.0f;
#pragma unroll
            for (int nt = 0; nt < 4; nt++) {
                float* a_ = acc[mt][nt];
                a1 += a_[0] * a_[0] + a_[1] * a_[1];
                a2 += a_[2] * a_[2] + a_[3] * a_[3];
            }
            a1 += __shfl_xor_sync(0xffffffffu, a1, 1);
            a1 += __shfl_xor_sync(0xffffffffu, a1, 2);
            a2 += __shfl_xor_sync(0xffffffffu, a2, 1);
            a2 += __shfl_xor_sync(0xffffffffu, a2, 2);
            s1[mt] = a1; s2[mt] = a2;
        }
        float* red = (float*)smem;   // [128 rows][4 wn] = 2 KB (stage smem reuse)
        __syncthreads();
        if (tig == 0) {
#pragma unroll
            for (int mt = 0; mt < 4; mt++) {
                int row = wm * 64 + mt * 16 + gq;
                red[row * 4 + wn]       = s1[mt];
                red[(row + 8) * 4 + wn] = s2[mt];
            }
        }
        __syncthreads();
#pragma unroll
        for (int mt = 0; mt < 4; mt++) {
            int row = wm * 64 + mt * 16 + gq;
            float t1 = red[row * 4] + red[row * 4 + 1] + red[row * 4 + 2] + red[row * 4 + 3];
            float t2 = red[(row + 8) * 4] + red[(row + 8) * 4 + 1] + red[(row + 8) * 4 + 2] + red[(row + 8) * 4 + 3];
            float sc1 = rsqrtf(t1 * (1.0f / 128.0f) + RMS_EPS);
            float sc2 = rsqrtf(t2 * (1.0f / 128.0f) + RMS_EPS);
#pragma unroll
            for (int nt = 0; nt < 4; nt++) {
                float* a_ = acc[mt][nt];
                a_[0] *= sc1; a_[1] *= sc1; a_[2] *= sc2; a_[3] *= sc2;
            }
        }
    } else if (region == 1) {
#pragma unroll
        for (int mt = 0; mt < 4; mt++)
#pragma unroll
            for (int nt = 0; nt < 4; nt++)
#pragma unroll
                for (int q = 0; q < 4; q++) acc[mt][nt][q] = tanhf(acc[mt][nt][q]);
    } else if (region == 3) {
#pragma unroll
        for (int mt = 0; mt < 4; mt++)
#pragma unroll
            for (int nt = 0; nt < 4; nt++)
#pragma unroll
                for (int q = 0; q < 4; q++)
                    acc[mt][nt][q] = fminf(fmaxf(sigm(acc[mt][nt][q] + 2.0f), 0.6f), 0.9995f);
    }

    // epilogue stores
#pragma unroll
    for (int mt = 0; mt < 4; mt++) {
        int mrow = m0 + wm * 64 + mt * 16 + gq;
#pragma unroll
        for (int nt = 0; nt < 4; nt++) {
            int ncol = n0 + wn * 32 + nt * 8 + tig * 2;
            float* a_ = acc[mt][nt];
            *(float2*)(C + (size_t)mrow * ldc + ncol)       = make_float2(a_[0], a_[1]);
            *(float2*)(C + (size_t)(mrow + 8) * ldc + ncol) = make_float2(a_[2], a_[3]);
        }
    }
#undef LOAD_STAGE
}

// ---------------------------------------------------------------------------
// split fp32 -> (bf16 hi, bf16 lo)
// ---------------------------------------------------------------------------
__global__ void split_kernel(const float* __restrict__ in, __nv_bfloat16* __restrict__ hi,
                             __nv_bfloat16* __restrict__ lo, int n4) {
    int i = blockIdx.x * blockDim.x + threadIdx.x;
    if (i >= n4) return;
    float4 v = ((const float4*)in)[i];
    __nv_bfloat16 h0 = __float2bfloat16(v.x), h1 = __float2bfloat16(v.y);
    __nv_bfloat16 h2 = __float2bfloat16(v.z), h3 = __float2bfloat16(v.w);
    __nv_bfloat16 l0 = __float2bfloat16(v.x - __bfloat162float(h0));
    __nv_bfloat16 l1 = __float2bfloat16(v.y - __bfloat162float(h1));
    __nv_bfloat16 l2 = __float2bfloat16(v.z - __bfloat162float(h2));
    __nv_bfloat16 l3 = __float2bfloat16(v.w - __bfloat162float(h3));
    ((__nv_bfloat162*)hi)[2 * i]     = __nv_bfloat162(h0, h1);
    ((__nv_bfloat162*)hi)[2 * i + 1] = __nv_bfloat162(h2, h3);
    ((__nv_bfloat162*)lo)[2 * i]     = __nv_bfloat162(l0, l1);
    ((__nv_bfloat162*)lo)[2 * i + 1] = __nv_bfloat162(l2, l3);
}

// ---------------------------------------------------------------------------
// Chunked scan. Slots in g_proj after GEMM1 epilogue transforms:
//   [0]=q_normed  [DD]=tanh(k)  [2DD]=v  [3DD]=a_clipped  [4DD]=g_raw
// ---------------------------------------------------------------------------
__global__ void scan_phase1() {
    const int d  = threadIdx.x;
    const int c  = blockIdx.x;
    const int bh = blockIdx.y;
    const int b  = bh >> 4, h = bh & 15;
    const int ch = bh * HDIM + d;

    const float* base = g_proj + ((size_t)(b * SS + c * CH)) * FD + h * HDIM + d;
    float p = 1.0f, acc = 0.0f;
#pragma unroll 8
    for (int t = 0; t < CH; t++) {
        float a  = base[(size_t)t * FD + 3 * DD];
        float tk = base[(size_t)t * FD + DD];
        float v  = base[(size_t)t * FD + 2 * DD];
        p *= a;
        acc += (tk * v) / fmaxf(p, 1e-6f);
    }
    g_P[c * NCHAN + ch] = p;
    g_A[c * NCHAN + ch] = acc;
}

// phase2: stage P/A in smem (parallel loads), then 64-step scan at smem latency
__global__ void scan_phase2() {
    extern __shared__ float sm2[];               // [2][64][128]
    float* sP = sm2;
    float* sA = sm2 + NCH * 128;
    const int t = threadIdx.x;
    const int ch0 = blockIdx.x * 128;
#pragma unroll 4
    for (int c = 0; c < NCH; c++) {
        sP[c * 128 + t] = g_P[c * NCHAN + ch0 + t];
        sA[c * 128 + t] = g_A[c * NCHAN + ch0 + t];
    }
    __syncthreads();
    float s = 0.0f;
#pragma unroll 8
    for (int c = 0; c < NCH; c++) {
        g_S0[c * NCHAN + ch0 + t] = s;
        s = sP[c * 128 + t] * (s + sA[c * 128 + t]);
    }
}

__global__ void scan_phase3() {
    const int d  = threadIdx.x;
    const int c  = blockIdx.x;
    const int bh = blockIdx.y;
    const int b  = bh >> 4, h = bh & 15;
    const int ch = bh * HDIM + d;

    const float* base = g_proj + ((size_t)(b * SS + c * CH)) * FD + h * HDIM + d;
    float s0 = g_S0[c * NCHAN + ch];
    float p = 1.0f, acc = 0.0f;
#pragma unroll 4
    for (int t = 0; t < CH; t++) {
        const float* row = base + (size_t)t * FD;
        float a  = row[3 * DD];
        float tk = row[DD];
        float v  = row[2 * DD];
        p *= a;
        acc += (tk * v) / fmaxf(p, 1e-6f);
        float mem = p * (s0 + acc);

        float qn = row[0];
        float gg = row[4 * DD];
        float gate = sigm(gg);
        float y = gate * (qn * mem) + (1.0f - gate) * v;

        size_t yi = (size_t)(b * SS + c * CH + t) * DD + h * HDIM + d;
        __nv_bfloat16 yh = __float2bfloat16(y);
        g_yh[yi] = yh;
        g_yl[yi] = __float2bfloat16(y - __bfloat162float(yh));
    }
}

// ---------------------------------------------------------------------------
extern "C" void kernel_launch(void* const* d_in, const int* in_sizes, int n_in,
                              void* d_out, int out_size) {
    const float* x     = (const float*)d_in[0];   // [2,4096,2048]
    const float* w_in  = (const float*)d_in[1];   // [10240,2048]
    const float* w_out = (const float*)d_in[2];   // [2048,2048]
    float* out = (float*)d_out;                   // [2,4096,2048]

    float* proj = nullptr;
    cudaGetSymbolAddress((void**)&proj, g_proj);
    __nv_bfloat16 *xh, *xl, *wih, *wil, *woh, *wol, *yh, *yl;
    cudaGetSymbolAddress((void**)&xh, g_xh);   cudaGetSymbolAddress((void**)&xl, g_xl);
    cudaGetSymbolAddress((void**)&wih, g_wih); cudaGetSymbolAddress((void**)&wil, g_wil);
    cudaGetSymbolAddress((void**)&woh, g_woh); cudaGetSymbolAddress((void**)&wol, g_wol);
    cudaGetSymbolAddress((void**)&yh, g_yh);   cudaGetSymbolAddress((void**)&yl, g_yl);

    cudaFuncSetAttribute(gemm_bf16x3_mma, cudaFuncAttributeMaxDynamicSharedMemorySize, GEMM_SMEM);
    cudaFuncSetAttribute(scan_phase2, cudaFuncAttributeMaxDynamicSharedMemorySize, 2 * NCH * 128 * 4);

    // split inputs to bf16 hi/lo
    {
        int n4;
        n4 = RB * DD / 4;  split_kernel<<<(n4 + 255) / 256, 256>>>(x, xh, xl, n4);
        n4 = FD * DD / 4;  split_kernel<<<(n4 + 255) / 256, 256>>>(w_in, wih, wil, n4);
        n4 = DD * DD / 4;  split_kernel<<<(n4 + 255) / 256, 256>>>(w_out, woh, wol, n4);
    }

    // GEMM1: proj = x @ w_in.T  (+ fused rmsnorm/tanh/sigmoid-clip epilogue)
    gemm_bf16x3_mma<<<(RB / 128) * (FD / 128), 256, GEMM_SMEM>>>(xh, xl, wih, wil, proj, FD / 128, FD, 1);

    // chunked scan
    scan_phase1<<<dim3(NCH, 32), 128>>>();
    scan_phase2<<<32, 128, 2 * NCH * 128 * 4>>>();
    scan_phase3<<<dim3(NCH, 32), 128>>>();

    // GEMM2: out = y @ w_out.T
    gemm_bf16x3_mma<<<(RB / 128) * (DD / 128), 256, GEMM_SMEM>>>(yh, yl, woh, wol, out, DD / 128, DD, 0);
}

// round 9
// speedup vs baseline: 1.5106x; 1.5106x over previous
#include <cuda_runtime.h>
#include <cuda_bf16.h>
#include <cstdint>

// Problem constants
#define RB    8192      // B*S rows
#define DD    2048      // D (= K for both GEMMs)
#define FD    10240     // 5*D
#define HH    16        // heads
#define HDIM  128      // head dim
#define CH    64        // chunk length
#define NCH   64        // number of chunks (S / CH)
#define NCHAN 4096      // B*H*HDIM channels
#define SS    4096      // S

#define BK    32
#define NKC   64        // K chunks (2048/32)
#define STAGE_BYTES 32768
#define NSTAGE 3
#define GEMM_SMEM (NSTAGE * STAGE_BYTES)

// ---------------- scratch (device globals; allocation-free) ----------------
__device__ float g_proj[(size_t)RB * FD];            // fp32 proj [8192,10240]
__device__ float g_P [NCH * NCHAN];
__device__ float g_A [NCH * NCHAN];
__device__ float g_S0[NCH * NCHAN];
__device__ __nv_bfloat16 g_xh[(size_t)RB * DD];
__device__ __nv_bfloat16 g_xl[(size_t)RB * DD];
__device__ __nv_bfloat16 g_wih[(size_t)FD * DD];
__device__ __nv_bfloat16 g_wil[(size_t)FD * DD];
__device__ __nv_bfloat16 g_woh[(size_t)DD * DD];
__device__ __nv_bfloat16 g_wol[(size_t)DD * DD];
__device__ __nv_bfloat16 g_yh[(size_t)RB * DD];
__device__ __nv_bfloat16 g_yl[(size_t)RB * DD];

// ---------------- helpers ----------------
__device__ __forceinline__ uint32_t smem_u32(const void* p) {
    uint32_t a;
    asm("{ .reg .u64 t; cvta.to.shared.u64 t, %1; cvt.u32.u64 %0, t; }" : "=r"(a) : "l"(p));
    return a;
}
__device__ __forceinline__ void cpasync16(uint32_t s, const void* g) {
    asm volatile("cp.async.cg.shared.global [%0], [%1], 16;\n" :: "r"(s), "l"(g) : "memory");
}
#define CP_COMMIT() asm volatile("cp.async.commit_group;\n" ::: "memory")
#define CP_WAIT(n)  asm volatile("cp.async.wait_group %0;\n" :: "n"(n) : "memory")

__device__ __forceinline__ void ldsm4(uint32_t& r0, uint32_t& r1, uint32_t& r2, uint32_t& r3, uint32_t a) {
    asm volatile("ldmatrix.sync.aligned.m8n8.x4.shared.b16 {%0,%1,%2,%3}, [%4];"
                 : "=r"(r0), "=r"(r1), "=r"(r2), "=r"(r3) : "r"(a));
}
__device__ __forceinline__ void mma16816(float& c0, float& c1, float& c2, float& c3,
                                         uint32_t a0, uint32_t a1, uint32_t a2, uint32_t a3,
                                         uint32_t b0, uint32_t b1) {
    asm volatile("mma.sync.aligned.m16n8k16.row.col.f32.bf16.bf16.f32 "
                 "{%0,%1,%2,%3}, {%4,%5,%6,%7}, {%8,%9}, {%0,%1,%2,%3};"
                 : "+f"(c0), "+f"(c1), "+f"(c2), "+f"(c3)
                 : "r"(a0), "r"(a1), "r"(a2), "r"(a3), "r"(b0), "r"(b1));
}

// smem tile layout: rows x BK(32) bf16, 4 chunks of 16B per row,
// chunk swizzled by (row>>1)&3 -> ldmatrix phases conflict-free
__device__ __forceinline__ uint32_t tile_off(int row, int c16) {
    return (uint32_t)((row * 4 + (c16 ^ ((row >> 1) & 3))) << 4);
}

// ---------------------------------------------------------------------------
// bf16 split-precision GEMM (TN): C[m,n] = sum_k A[m,k]*B[n,k], K = 2048.
// Computes Ah*Bh + Al*Bh + Ah*Bl via mma.sync m16n8k16, fp32 accum.
// CTA 128x128, BK=32, 3-stage cp.async pipeline, 256 threads, 2 CTAs/SM.
// (R6 champion — unmodified; epilogue fusion regressed this kernel in R7.)
// ---------------------------------------------------------------------------
__global__ __launch_bounds__(256, 2)
void gemm_bf16x3_mma(const __nv_bfloat16* __restrict__ Ah, const __nv_bfloat16* __restrict__ Al,
                     const __nv_bfloat16* __restrict__ Bh, const __nv_bfloat16* __restrict__ Bl,
                     float* __restrict__ C, int nb_n, int ldc) {
    extern __shared__ char smem[];
    const uint32_t sb = smem_u32(smem);
    const int tid  = threadIdx.x;
    const int wid  = tid >> 5;
    const int lane = tid & 31;

    // supertile swizzle for L2: groups of W m-blocks, m fast
    const int W = 16;
    int id = blockIdx.x;
    int gsize = W * nb_n;
    int g = id / gsize, r = id % gsize;
    int m0 = (g * W + (r % W)) << 7;
    int n0 = (r / W) << 7;

    const int wm = wid & 1;        // 0..1
    const int wn = wid >> 1;       // 0..3

    // per-thread load coords (2 chunks per tile per thread)
    const int lrow0 = tid >> 2;
    const int lc0   = tid & 3;
    const int lrow1 = (tid + 256) >> 2;
    const int lc1   = (tid + 256) & 3;
    const uint32_t so0 = tile_off(lrow0, lc0);
    const uint32_t so1 = tile_off(lrow1, lc1);

#define LOAD_STAGE(sidx, k0)                                                     \
    do {                                                                         \
        uint32_t stb = sb + (sidx) * STAGE_BYTES;                                \
        size_t gA0 = (size_t)(m0 + lrow0) * DD + (k0) + lc0 * 8;                 \
        size_t gA1 = (size_t)(m0 + lrow1) * DD + (k0) + lc1 * 8;                 \
        size_t gB0 = (size_t)(n0 + lrow0) * DD + (k0) + lc0 * 8;                 \
        size_t gB1 = (size_t)(n0 + lrow1) * DD + (k0) + lc1 * 8;                 \
        cpasync16(stb + so0,          Ah + gA0);                                 \
        cpasync16(stb + so1,          Ah + gA1);                                 \
        cpasync16(stb + 8192 + so0,   Al + gA0);                                 \
        cpasync16(stb + 8192 + so1,   Al + gA1);                                 \
        cpasync16(stb + 16384 + so0,  Bh + gB0);                                 \
        cpasync16(stb + 16384 + so1,  Bh + gB1);                                 \
        cpasync16(stb + 24576 + so0,  Bl + gB0);                                 \
        cpasync16(stb + 24576 + so1,  Bl + gB1);                                 \
        CP_COMMIT();                                                             \
    } while (0)

    LOAD_STAGE(0, 0);
    LOAD_STAGE(1, BK);

    float acc[4][4][4];
#pragma unroll
    for (int i = 0; i < 4; i++)
#pragma unroll
        for (int j = 0; j < 4; j++)
#pragma unroll
            for (int q = 0; q < 4; q++) acc[i][j][q] = 0.0f;

    const int lj = lane >> 3;
    const int li = lane & 7;

    for (int it = 0; it < NKC; it++) {
        if (it < NKC - 1) { CP_WAIT(1); } else { CP_WAIT(0); }
        __syncthreads();

        if (it + 2 < NKC) LOAD_STAGE((it + 2) % NSTAGE, (it + 2) * BK);

        uint32_t stb = sb + (it % NSTAGE) * STAGE_BYTES;
        uint32_t sAh = stb, sAl = stb + 8192, sBh = stb + 16384, sBl = stb + 24576;

#pragma unroll
        for (int h = 0; h < 2; h++) {
            uint32_t bh[8], bl[8];
#pragma unroll
            for (int ntp = 0; ntp < 2; ntp++) {
                int brow = wn * 32 + ntp * 16 + ((lj >> 1) * 8) + li;
                int bc16 = 2 * h + (lj & 1);
                uint32_t boff = tile_off(brow, bc16);
                ldsm4(bh[ntp * 4], bh[ntp * 4 + 1], bh[ntp * 4 + 2], bh[ntp * 4 + 3], sBh + boff);
                ldsm4(bl[ntp * 4], bl[ntp * 4 + 1], bl[ntp * 4 + 2], bl[ntp * 4 + 3], sBl + boff);
            }
#pragma unroll
            for (int mt = 0; mt < 4; mt++) {
                int arow = wm * 64 + mt * 16 + ((lj & 1) * 8) + li;
                int ac16 = 2 * h + (lj >> 1);
                uint32_t aoff = tile_off(arow, ac16);
                uint32_t ah0, ah1, ah2, ah3, al0, al1, al2, al3;
                ldsm4(ah0, ah1, ah2, ah3, sAh + aoff);
                ldsm4(al0, al1, al2, al3, sAl + aoff);
#pragma unroll
                for (int ntp = 0; ntp < 2; ntp++) {
#pragma unroll
                    for (int s = 0; s < 2; s++) {
                        int nt = ntp * 2 + s;
                        uint32_t b0h = bh[ntp * 4 + s * 2], b1h = bh[ntp * 4 + s * 2 + 1];
                        uint32_t b0l = bl[ntp * 4 + s * 2], b1l = bl[ntp * 4 + s * 2 + 1];
                        float* a_ = acc[mt][nt];
                        mma16816(a_[0], a_[1], a_[2], a_[3], ah0, ah1, ah2, ah3, b0h, b1h);
                        mma16816(a_[0], a_[1], a_[2], a_[3], al0, al1, al2, al3, b0h, b1h);
                        mma16816(a_[0], a_[1], a_[2], a_[3], ah0, ah1, ah2, ah3, b0l, b1l);
                    }
                }
            }
        }
    }

    // epilogue: direct fp32 stores
    const int gq  = lane >> 2;
    const int tig = lane & 3;
#pragma unroll
    for (int mt = 0; mt < 4; mt++) {
        int mrow = m0 + wm * 64 + mt * 16 + gq;
#pragma unroll
        for (int nt = 0; nt < 4; nt++) {
            int ncol = n0 + wn * 32 + nt * 8 + tig * 2;
            float* a_ = acc[mt][nt];
            *(float2*)(C + (size_t)mrow * ldc + ncol)       = make_float2(a_[0], a_[1]);
            *(float2*)(C + (size_t)(mrow + 8) * ldc + ncol) = make_float2(a_[2], a_[3]);
        }
    }
#undef LOAD_STAGE
}

// ---------------------------------------------------------------------------
// split fp32 -> (bf16 hi, bf16 lo)
// ---------------------------------------------------------------------------
__global__ void split_kernel(const float* __restrict__ in, __nv_bfloat16* __restrict__ hi,
                             __nv_bfloat16* __restrict__ lo, int n4) {
    int i = blockIdx.x * blockDim.x + threadIdx.x;
    if (i >= n4) return;
    float4 v = ((const float4*)in)[i];
    __nv_bfloat16 h0 = __float2bfloat16(v.x), h1 = __float2bfloat16(v.y);
    __nv_bfloat16 h2 = __float2bfloat16(v.z), h3 = __float2bfloat16(v.w);
    __nv_bfloat16 l0 = __float2bfloat16(v.x - __bfloat162float(h0));
    __nv_bfloat16 l1 = __float2bfloat16(v.y - __bfloat162float(h1));
    __nv_bfloat16 l2 = __float2bfloat16(v.z - __bfloat162float(h2));
    __nv_bfloat16 l3 = __float2bfloat16(v.w - __bfloat162float(h3));
    ((__nv_bfloat162*)hi)[2 * i]     = __nv_bfloat162(h0, h1);
    ((__nv_bfloat162*)hi)[2 * i + 1] = __nv_bfloat162(h2, h3);
    ((__nv_bfloat162*)lo)[2 * i]     = __nv_bfloat162(l0, l1);
    ((__nv_bfloat162*)lo)[2 * i + 1] = __nv_bfloat162(l2, l3);
}

// ---------------------------------------------------------------------------
// Elementwise prep (in place on g_proj): q<-rmsnorm(q); k-slot<-u=tanh(k)*v;
// a-slot<-clip(sigmoid(a+2))
// ---------------------------------------------------------------------------
__global__ void prep_kernel() {
    const int d = threadIdx.x;
    const int h = blockIdx.x;
    const int r = blockIdx.y;
    float* row = g_proj + (size_t)r * FD + h * HDIM + d;

    float q    = row[0];
    float k    = row[DD];
    float v    = row[2 * DD];
    float a_in = row[3 * DD];

    float ss = q * q;
#pragma unroll
    for (int o = 16; o > 0; o >>= 1) ss += __shfl_xor_sync(0xffffffffu, ss, o);
    __shared__ float red[4];
    if ((d & 31) == 0) red[d >> 5] = ss;
    __syncthreads();
    float sum = red[0] + red[1] + red[2] + red[3];

    float qn = q * rsqrtf(sum * (1.0f / 128.0f) + 1.1920928955078125e-07f);
    float u  = tanhf(k) * v;
    float sg = 1.0f / (1.0f + expf(-(a_in + 2.0f)));
    float a  = fminf(fmaxf(sg, 0.6f), 0.9995f);

    row[0]      = qn;
    row[DD]     = u;
    row[3 * DD] = a;
}

// ---------------------------------------------------------------------------
// Chunked scan phases (clamped-cumprod math identical to reference)
// ---------------------------------------------------------------------------
__global__ void scan_phase1() {
    const int d  = threadIdx.x;
    const int c  = blockIdx.x;
    const int bh = blockIdx.y;
    const int b  = bh >> 4, h = bh & 15;
    const int ch = bh * HDIM + d;

    const float* base = g_proj + ((size_t)(b * SS + c * CH)) * FD + h * HDIM + d;
    float p = 1.0f, acc = 0.0f;
#pragma unroll 8
    for (int t = 0; t < CH; t++) {
        float a = base[(size_t)t * FD + 3 * DD];
        float u = base[(size_t)t * FD + DD];
        p *= a;
        acc += u / fmaxf(p, 1e-6f);
    }
    g_P[c * NCHAN + ch] = p;
    g_A[c * NCHAN + ch] = acc;
}

// phase2: stage P/A in smem (parallel coalesced loads), then scan at smem latency
__global__ void scan_phase2() {
    extern __shared__ float sm2[];               // [2][64][128] = 64 KB
    float* sP = sm2;
    float* sA = sm2 + NCH * 128;
    const int t = threadIdx.x;
    const int ch0 = blockIdx.x * 128;
#pragma unroll 4
    for (int c = 0; c < NCH; c++) {
        sP[c * 128 + t] = g_P[c * NCHAN + ch0 + t];
        sA[c * 128 + t] = g_A[c * NCHAN + ch0 + t];
    }
    __syncthreads();
    float s = 0.0f;
#pragma unroll 8
    for (int c = 0; c < NCH; c++) {
        g_S0[c * NCHAN + ch0 + t] = s;
        s = sP[c * 128 + t] * (s + sA[c * 128 + t]);
    }
}

__global__ void scan_phase3() {
    const int d  = threadIdx.x;
    const int c  = blockIdx.x;
    const int bh = blockIdx.y;
    const int b  = bh >> 4, h = bh & 15;
    const int ch = bh * HDIM + d;

    const float* base = g_proj + ((size_t)(b * SS + c * CH)) * FD + h * HDIM + d;
    float s0 = g_S0[c * NCHAN + ch];
    float p = 1.0f, acc = 0.0f;
#pragma unroll 4
    for (int t = 0; t < CH; t++) {
        const float* row = base + (size_t)t * FD;
        float a = row[3 * DD];
        float u = row[DD];
        p *= a;
        acc += u / fmaxf(p, 1e-6f);
        float mem = p * (s0 + acc);

        float qn = row[0];
        float v  = row[2 * DD];
        float gg = row[4 * DD];
        float gate = 1.0f / (1.0f + expf(-gg));
        float y = gate * (qn * mem) + (1.0f - gate) * v;

        size_t yi = (size_t)(b * SS + c * CH + t) * DD + h * HDIM + d;
        __nv_bfloat16 yh = __float2bfloat16(y);
        g_yh[yi] = yh;
        g_yl[yi] = __float2bfloat16(y - __bfloat162float(yh));
    }
}

// ---------------------------------------------------------------------------
extern "C" void kernel_launch(void* const* d_in, const int* in_sizes, int n_in,
                              void* d_out, int out_size) {
    const float* x     = (const float*)d_in[0];   // [2,4096,2048]
    const float* w_in  = (const float*)d_in[1];   // [10240,2048]
    const float* w_out = (const float*)d_in[2];   // [2048,2048]
    float* out = (float*)d_out;                   // [2,4096,2048]

    float* proj = nullptr;
    cudaGetSymbolAddress((void**)&proj, g_proj);
    __nv_bfloat16 *xh, *xl, *wih, *wil, *woh, *wol, *yh, *yl;
    cudaGetSymbolAddress((void**)&xh, g_xh);   cudaGetSymbolAddress((void**)&xl, g_xl);
    cudaGetSymbolAddress((void**)&wih, g_wih); cudaGetSymbolAddress((void**)&wil, g_wil);
    cudaGetSymbolAddress((void**)&woh, g_woh); cudaGetSymbolAddress((void**)&wol, g_wol);
    cudaGetSymbolAddress((void**)&yh, g_yh);   cudaGetSymbolAddress((void**)&yl, g_yl);

    cudaFuncSetAttribute(gemm_bf16x3_mma, cudaFuncAttributeMaxDynamicSharedMemorySize, GEMM_SMEM);
    cudaFuncSetAttribute(scan_phase2, cudaFuncAttributeMaxDynamicSharedMemorySize, 2 * NCH * 128 * 4);

    // split inputs to bf16 hi/lo
    {
        int n4;
        n4 = RB * DD / 4;  split_kernel<<<(n4 + 255) / 256, 256>>>(x, xh, xl, n4);
        n4 = FD * DD / 4;  split_kernel<<<(n4 + 255) / 256, 256>>>(w_in, wih, wil, n4);
        n4 = DD * DD / 4;  split_kernel<<<(n4 + 255) / 256, 256>>>(w_out, woh, wol, n4);
    }

    // GEMM1: proj = x @ w_in.T   [8192 x 10240]
    gemm_bf16x3_mma<<<(RB / 128) * (FD / 128), 256, GEMM_SMEM>>>(xh, xl, wih, wil, proj, FD / 128, FD);

    // elementwise + chunked scan
    prep_kernel<<<dim3(HH, RB), 128>>>();
    scan_phase1<<<dim3(NCH, 32), 128>>>();
    scan_phase2<<<32, 128, 2 * NCH * 128 * 4>>>();
    scan_phase3<<<dim3(NCH, 32), 128>>>();

    // GEMM2: out = y @ w_out.T   [8192 x 2048]
    gemm_bf16x3_mma<<<(RB / 128) * (DD / 128), 256, GEMM_SMEM>>>(yh, yl, woh, wol, out, DD / 128, DD);
}

// round 13
// speedup vs baseline: 1.5502x; 1.0262x over previous
#include <cuda_runtime.h>
#include <cuda_bf16.h>
#include <cstdint>

// Problem constants
#define RB    8192      // B*S rows
#define DD    2048      // D (= K for both GEMMs)
#define FD    10240     // 5*D
#define HH    16        // heads
#define HDIM  128       // head dim
#define CH    64        // chunk length
#define NCH   64        // number of chunks (S / CH)
#define NCHAN 4096      // B*H*HDIM channels
#define SS    4096      // S
#define RMS_EPS 1.1920928955078125e-07f

#define BK    32
#define NKC   64        // K chunks (2048/32)
#define STAGE_BYTES 32768
#define NSTAGE 3
#define GEMM_SMEM (NSTAGE * STAGE_BYTES)

// ---------------- scratch (device globals; allocation-free) ----------------
__device__ float g_proj[(size_t)RB * FD];            // fp32 proj [8192,10240] (raw GEMM1 output)
__device__ float g_P [NCH * NCHAN];
__device__ float g_A [NCH * NCHAN];
__device__ float g_S0[NCH * NCHAN];
__device__ __nv_bfloat16 g_xh[(size_t)RB * DD];
__device__ __nv_bfloat16 g_xl[(size_t)RB * DD];
__device__ __nv_bfloat16 g_wih[(size_t)FD * DD];
__device__ __nv_bfloat16 g_wil[(size_t)FD * DD];
__device__ __nv_bfloat16 g_woh[(size_t)DD * DD];
__device__ __nv_bfloat16 g_wol[(size_t)DD * DD];
__device__ __nv_bfloat16 g_yh[(size_t)RB * DD];
__device__ __nv_bfloat16 g_yl[(size_t)RB * DD];

// ---------------- helpers ----------------
__device__ __forceinline__ uint32_t smem_u32(const void* p) {
    uint32_t a;
    asm("{ .reg .u64 t; cvta.to.shared.u64 t, %1; cvt.u32.u64 %0, t; }" : "=r"(a) : "l"(p));
    return a;
}
__device__ __forceinline__ void cpasync16(uint32_t s, const void* g) {
    asm volatile("cp.async.cg.shared.global [%0], [%1], 16;\n" :: "r"(s), "l"(g) : "memory");
}
#define CP_COMMIT() asm volatile("cp.async.commit_group;\n" ::: "memory")
#define CP_WAIT(n)  asm volatile("cp.async.wait_group %0;\n" :: "n"(n) : "memory")

__device__ __forceinline__ void ldsm4(uint32_t& r0, uint32_t& r1, uint32_t& r2, uint32_t& r3, uint32_t a) {
    asm volatile("ldmatrix.sync.aligned.m8n8.x4.shared.b16 {%0,%1,%2,%3}, [%4];"
                 : "=r"(r0), "=r"(r1), "=r"(r2), "=r"(r3) : "r"(a));
}
__device__ __forceinline__ void mma16816(float& c0, float& c1, float& c2, float& c3,
                                         uint32_t a0, uint32_t a1, uint32_t a2, uint32_t a3,
                                         uint32_t b0, uint32_t b1) {
    asm volatile("mma.sync.aligned.m16n8k16.row.col.f32.bf16.bf16.f32 "
                 "{%0,%1,%2,%3}, {%4,%5,%6,%7}, {%8,%9}, {%0,%1,%2,%3};"
                 : "+f"(c0), "+f"(c1), "+f"(c2), "+f"(c3)
                 : "r"(a0), "r"(a1), "r"(a2), "r"(a3), "r"(b0), "r"(b1));
}

// smem tile layout: rows x BK(32) bf16, 4 chunks of 16B per row,
// chunk swizzled by (row>>1)&3 -> ldmatrix phases conflict-free
__device__ __forceinline__ uint32_t tile_off(int row, int c16) {
    return (uint32_t)((row * 4 + (c16 ^ ((row >> 1) & 3))) << 4);
}

__device__ __forceinline__ float sigm(float x) { return 1.0f / (1.0f + expf(-x)); }

// ---------------------------------------------------------------------------
// bf16 split-precision GEMM (TN): C[m,n] = sum_k A[m,k]*B[n,k], K = 2048.
// Computes Ah*Bh + Al*Bh + Ah*Bl via mma.sync m16n8k16, fp32 accum.
// CTA 128x128, BK=32, 3-stage cp.async pipeline, 256 threads, 2 CTAs/SM.
// (R6 champion — DO NOT MODIFY; any code growth regresses it: see R7.)
// ---------------------------------------------------------------------------
__global__ __launch_bounds__(256, 2)
void gemm_bf16x3_mma(const __nv_bfloat16* __restrict__ Ah, const __nv_bfloat16* __restrict__ Al,
                     const __nv_bfloat16* __restrict__ Bh, const __nv_bfloat16* __restrict__ Bl,
                     float* __restrict__ C, int nb_n, int ldc) {
    extern __shared__ char smem[];
    const uint32_t sb = smem_u32(smem);
    const int tid  = threadIdx.x;
    const int wid  = tid >> 5;
    const int lane = tid & 31;

    // supertile swizzle for L2: groups of W m-blocks, m fast
    const int W = 16;
    int id = blockIdx.x;
    int gsize = W * nb_n;
    int g = id / gsize, r = id % gsize;
    int m0 = (g * W + (r % W)) << 7;
    int n0 = (r / W) << 7;

    const int wm = wid & 1;        // 0..1
    const int wn = wid >> 1;       // 0..3

    // per-thread load coords (2 chunks per tile per thread)
    const int lrow0 = tid >> 2;
    const int lc0   = tid & 3;
    const int lrow1 = (tid + 256) >> 2;
    const int lc1   = (tid + 256) & 3;
    const uint32_t so0 = tile_off(lrow0, lc0);
    const uint32_t so1 = tile_off(lrow1, lc1);

#define LOAD_STAGE(sidx, k0)                                                     \
    do {                                                                         \
        uint32_t stb = sb + (sidx) * STAGE_BYTES;                                \
        size_t gA0 = (size_t)(m0 + lrow0) * DD + (k0) + lc0 * 8;                 \
        size_t gA1 = (size_t)(m0 + lrow1) * DD + (k0) + lc1 * 8;                 \
        size_t gB0 = (size_t)(n0 + lrow0) * DD + (k0) + lc0 * 8;                 \
        size_t gB1 = (size_t)(n0 + lrow1) * DD + (k0) + lc1 * 8;                 \
        cpasync16(stb + so0,          Ah + gA0);                                 \
        cpasync16(stb + so1,          Ah + gA1);                                 \
        cpasync16(stb + 8192 + so0,   Al + gA0);                                 \
        cpasync16(stb + 8192 + so1,   Al + gA1);                                 \
        cpasync16(stb + 16384 + so0,  Bh + gB0);                                 \
        cpasync16(stb + 16384 + so1,  Bh + gB1);                                 \
        cpasync16(stb + 24576 + so0,  Bl + gB0);                                 \
        cpasync16(stb + 24576 + so1,  Bl + gB1);                                 \
        CP_COMMIT();                                                             \
    } while (0)

    LOAD_STAGE(0, 0);
    LOAD_STAGE(1, BK);

    float acc[4][4][4];
#pragma unroll
    for (int i = 0; i < 4; i++)
#pragma unroll
        for (int j = 0; j < 4; j++)
#pragma unroll
            for (int q = 0; q < 4; q++) acc[i][j][q] = 0.0f;

    const int lj = lane >> 3;
    const int li = lane & 7;

    for (int it = 0; it < NKC; it++) {
        if (it < NKC - 1) { CP_WAIT(1); } else { CP_WAIT(0); }
        __syncthreads();

        if (it + 2 < NKC) LOAD_STAGE((it + 2) % NSTAGE, (it + 2) * BK);

        uint32_t stb = sb + (it % NSTAGE) * STAGE_BYTES;
        uint32_t sAh = stb, sAl = stb + 8192, sBh = stb + 16384, sBl = stb + 24576;

#pragma unroll
        for (int h = 0; h < 2; h++) {
            uint32_t bh[8], bl[8];
#pragma unroll
            for (int ntp = 0; ntp < 2; ntp++) {
                int brow = wn * 32 + ntp * 16 + ((lj >> 1) * 8) + li;
                int bc16 = 2 * h + (lj & 1);
                uint32_t boff = tile_off(brow, bc16);
                ldsm4(bh[ntp * 4], bh[ntp * 4 + 1], bh[ntp * 4 + 2], bh[ntp * 4 + 3], sBh + boff);
                ldsm4(bl[ntp * 4], bl[ntp * 4 + 1], bl[ntp * 4 + 2], bl[ntp * 4 + 3], sBl + boff);
            }
#pragma unroll
            for (int mt = 0; mt < 4; mt++) {
                int arow = wm * 64 + mt * 16 + ((lj & 1) * 8) + li;
                int ac16 = 2 * h + (lj >> 1);
                uint32_t aoff = tile_off(arow, ac16);
                uint32_t ah0, ah1, ah2, ah3, al0, al1, al2, al3;
                ldsm4(ah0, ah1, ah2, ah3, sAh + aoff);
                ldsm4(al0, al1, al2, al3, sAl + aoff);
#pragma unroll
                for (int ntp = 0; ntp < 2; ntp++) {
#pragma unroll
                    for (int s = 0; s < 2; s++) {
                        int nt = ntp * 2 + s;
                        uint32_t b0h = bh[ntp * 4 + s * 2], b1h = bh[ntp * 4 + s * 2 + 1];
                        uint32_t b0l = bl[ntp * 4 + s * 2], b1l = bl[ntp * 4 + s * 2 + 1];
                        float* a_ = acc[mt][nt];
                        mma16816(a_[0], a_[1], a_[2], a_[3], ah0, ah1, ah2, ah3, b0h, b1h);
                        mma16816(a_[0], a_[1], a_[2], a_[3], al0, al1, al2, al3, b0h, b1h);
                        mma16816(a_[0], a_[1], a_[2], a_[3], ah0, ah1, ah2, ah3, b0l, b1l);
                    }
                }
            }
        }
    }

    // epilogue: direct fp32 stores
    const int gq  = lane >> 2;
    const int tig = lane & 3;
#pragma unroll
    for (int mt = 0; mt < 4; mt++) {
        int mrow = m0 + wm * 64 + mt * 16 + gq;
#pragma unroll
        for (int nt = 0; nt < 4; nt++) {
            int ncol = n0 + wn * 32 + nt * 8 + tig * 2;
            float* a_ = acc[mt][nt];
            *(float2*)(C + (size_t)mrow * ldc + ncol)       = make_float2(a_[0], a_[1]);
            *(float2*)(C + (size_t)(mrow + 8) * ldc + ncol) = make_float2(a_[2], a_[3]);
        }
    }
#undef LOAD_STAGE
}

// ---------------------------------------------------------------------------
// split fp32 -> (bf16 hi, bf16 lo)
// ---------------------------------------------------------------------------
__global__ void split_kernel(const float* __restrict__ in, __nv_bfloat16* __restrict__ hi,
                             __nv_bfloat16* __restrict__ lo, int n4) {
    int i = blockIdx.x * blockDim.x + threadIdx.x;
    if (i >= n4) return;
    float4 v = ((const float4*)in)[i];
    __nv_bfloat16 h0 = __float2bfloat16(v.x), h1 = __float2bfloat16(v.y);
    __nv_bfloat16 h2 = __float2bfloat16(v.z), h3 = __float2bfloat16(v.w);
    __nv_bfloat16 l0 = __float2bfloat16(v.x - __bfloat162float(h0));
    __nv_bfloat16 l1 = __float2bfloat16(v.y - __bfloat162float(h1));
    __nv_bfloat16 l2 = __float2bfloat16(v.z - __bfloat162float(h2));
    __nv_bfloat16 l3 = __float2bfloat16(v.w - __bfloat162float(h3));
    ((__nv_bfloat162*)hi)[2 * i]     = __nv_bfloat162(h0, h1);
    ((__nv_bfloat162*)hi)[2 * i + 1] = __nv_bfloat162(h2, h3);
    ((__nv_bfloat162*)lo)[2 * i]     = __nv_bfloat162(l0, l1);
    ((__nv_bfloat162*)lo)[2 * i + 1] = __nv_bfloat162(l2, l3);
}

// ---------------------------------------------------------------------------
// Chunked scan over RAW proj (no prep pass). Transforms recomputed inline:
//   u = tanh(k_raw) * v,  a = clip(sigmoid(a_raw + 2), 0.6, 0.9995)
// phase3 additionally recomputes q rmsnorm (block = one head's 128 dims).
// ---------------------------------------------------------------------------
__global__ void scan_phase1() {
    const int d  = threadIdx.x;
    const int c  = blockIdx.x;
    const int bh = blockIdx.y;
    const int b  = bh >> 4, h = bh & 15;
    const int ch = bh * HDIM + d;

    const float* base = g_proj + ((size_t)(b * SS + c * CH)) * FD + h * HDIM + d;
    float p = 1.0f, acc = 0.0f;
#pragma unroll 4
    for (int t = 0; t < CH; t++) {
        float kraw = base[(size_t)t * FD + DD];
        float v    = base[(size_t)t * FD + 2 * DD];
        float araw = base[(size_t)t * FD + 3 * DD];
        float a = fminf(fmaxf(sigm(araw + 2.0f), 0.6f), 0.9995f);
        float u = tanhf(kraw) * v;
        p *= a;
        acc += u / fmaxf(p, 1e-6f);
    }
    g_P[c * NCHAN + ch] = p;
    g_A[c * NCHAN + ch] = acc;
}

// phase2: stage P/A in smem (parallel coalesced loads), then scan at smem latency
__global__ void scan_phase2() {
    extern __shared__ float sm2[];               // [2][64][128] = 64 KB
    float* sP = sm2;
    float* sA = sm2 + NCH * 128;
    const int t = threadIdx.x;
    const int ch0 = blockIdx.x * 128;
#pragma unroll 4
    for (int c = 0; c < NCH; c++) {
        sP[c * 128 + t] = g_P[c * NCHAN + ch0 + t];
        sA[c * 128 + t] = g_A[c * NCHAN + ch0 + t];
    }
    __syncthreads();
    float s = 0.0f;
#pragma unroll 8
    for (int c = 0; c < NCH; c++) {
        g_S0[c * NCHAN + ch0 + t] = s;
        s = sP[c * 128 + t] * (s + sA[c * 128 + t]);
    }
}

// phase3: replay from raw slots; recompute rmsnorm/tanh/sigmoid; emit y hi/lo
__global__ void scan_phase3() {
    const int d  = threadIdx.x;
    const int c  = blockIdx.x;
    const int bh = blockIdx.y;
    const int b  = bh >> 4, h = bh & 15;
    const int ch = bh * HDIM + d;

    __shared__ float red[4];

    const float* base = g_proj + ((size_t)(b * SS + c * CH)) * FD + h * HDIM + d;
    float s0 = g_S0[c * NCHAN + ch];
    float p = 1.0f, acc = 0.0f;
    for (int t = 0; t < CH; t++) {
        const float* row = base + (size_t)t * FD;
        float q    = row[0];
        float kraw = row[DD];
        float v    = row[2 * DD];
        float araw = row[3 * DD];
        float gg   = row[4 * DD];

        // rmsnorm over this head's 128 dims (block-wide reduction)
        float ss = q * q;
#pragma unroll
        for (int o = 16; o > 0; o >>= 1) ss += __shfl_xor_sync(0xffffffffu, ss, o);
        if ((d & 31) == 0) red[d >> 5] = ss;
        __syncthreads();
        float sum = red[0] + red[1] + red[2] + red[3];
        __syncthreads();
        float qn = q * rsqrtf(sum * (1.0f / 128.0f) + RMS_EPS);

        float a = fminf(fmaxf(sigm(araw + 2.0f), 0.6f), 0.9995f);
        float u = tanhf(kraw) * v;
        p *= a;
        acc += u / fmaxf(p, 1e-6f);
        float mem = p * (s0 + acc);

        float gate = sigm(gg);
        float y = gate * (qn * mem) + (1.0f - gate) * v;

        size_t yi = (size_t)(b * SS + c * CH + t) * DD + h * HDIM + d;
        __nv_bfloat16 yh = __float2bfloat16(y);
        g_yh[yi] = yh;
        g_yl[yi] = __float2bfloat16(y - __bfloat162float(yh));
    }
}

// ---------------------------------------------------------------------------
extern "C" void kernel_launch(void* const* d_in, const int* in_sizes, int n_in,
                              void* d_out, int out_size) {
    const float* x     = (const float*)d_in[0];   // [2,4096,2048]
    const float* w_in  = (const float*)d_in[1];   // [10240,2048]
    const float* w_out = (const float*)d_in[2];   // [2048,2048]
    float* out = (float*)d_out;                   // [2,4096,2048]

    float* proj = nullptr;
    cudaGetSymbolAddress((void**)&proj, g_proj);
    __nv_bfloat16 *xh, *xl, *wih, *wil, *woh, *wol, *yh, *yl;
    cudaGetSymbolAddress((void**)&xh, g_xh);   cudaGetSymbolAddress((void**)&xl, g_xl);
    cudaGetSymbolAddress((void**)&wih, g_wih); cudaGetSymbolAddress((void**)&wil, g_wil);
    cudaGetSymbolAddress((void**)&woh, g_woh); cudaGetSymbolAddress((void**)&wol, g_wol);
    cudaGetSymbolAddress((void**)&yh, g_yh);   cudaGetSymbolAddress((void**)&yl, g_yl);

    cudaFuncSetAttribute(gemm_bf16x3_mma, cudaFuncAttributeMaxDynamicSharedMemorySize, GEMM_SMEM);
    cudaFuncSetAttribute(scan_phase2, cudaFuncAttributeMaxDynamicSharedMemorySize, 2 * NCH * 128 * 4);

    // split inputs to bf16 hi/lo
    {
        int n4;
        n4 = RB * DD / 4;  split_kernel<<<(n4 + 255) / 256, 256>>>(x, xh, xl, n4);
        n4 = FD * DD / 4;  split_kernel<<<(n4 + 255) / 256, 256>>>(w_in, wih, wil, n4);
        n4 = DD * DD / 4;  split_kernel<<<(n4 + 255) / 256, 256>>>(w_out, woh, wol, n4);
    }

    // GEMM1: proj = x @ w_in.T   [8192 x 10240]  (raw; transforms live in scan)
    gemm_bf16x3_mma<<<(RB / 128) * (FD / 128), 256, GEMM_SMEM>>>(xh, xl, wih, wil, proj, FD / 128, FD);

    // chunked scan (prep fused in)
    scan_phase1<<<dim3(NCH, 32), 128>>>();
    scan_phase2<<<32, 128, 2 * NCH * 128 * 4>>>();
    scan_phase3<<<dim3(NCH, 32), 128>>>();

    // GEMM2: out = y @ w_out.T   [8192 x 2048]
    gemm_bf16x3_mma<<<(RB / 128) * (DD / 128), 256, GEMM_SMEM>>>(yh, yl, woh, wol, out, DD / 128, DD);
}